// round 6
// baseline (speedup 1.0000x reference)
#include <cuda_runtime.h>
#include <cuda_bf16.h>
#include <float.h>
#include <stdint.h>

// ---------------------------------------------------------------------------
// MVCNN fused single persistent kernel: pool -> [gemm -> reduce] x3
// GEMM: mma.sync.m16n8k16 bf16 hi/lo (3 MMAs), f32 acc. R5-proven internals.
// Grid barriers: sense-reversing, self-resetting (replay-safe).
// 256 CTAs x 256 thr, 2 CTAs/SM guaranteed resident.
// ---------------------------------------------------------------------------

#define BATCH 64
#define DIM   4096
#define VIEWS 256
#define OUTN  1000
#define NCTA  256

__device__ __align__(256) __nv_bfloat16 g_actH[BATCH * DIM];
__device__ __align__(256) __nv_bfloat16 g_actL[BATCH * DIM];
__device__ __align__(256) float g_part[16][DIM * BATCH];  // [ksplit][feat][batch]

__device__ unsigned g_cnt = 0;
__device__ unsigned g_gen = 0;   // monotonic across graph replays

// ---------------------------------------------------------------------------
// helpers
// ---------------------------------------------------------------------------
__device__ __forceinline__ uint32_t smem_u32(const void* p) {
    uint32_t a;
    asm("{ .reg .u64 t; cvta.to.shared.u64 t, %1; cvt.u32.u64 %0, t; }"
        : "=r"(a) : "l"(p));
    return a;
}
__device__ __forceinline__ void cp16(uint32_t dst, const void* src) {
    asm volatile("cp.async.cg.shared.global [%0], [%1], 16;"
                 :: "r"(dst), "l"(src));
}
__device__ __forceinline__ void cp_commit() {
    asm volatile("cp.async.commit_group;" ::: "memory");
}
template<int N> __device__ __forceinline__ void cp_wait() {
    asm volatile("cp.async.wait_group %0;" :: "n"(N) : "memory");
}
__device__ __forceinline__ void ldsm4(uint32_t* r, uint32_t a) {
    asm volatile("ldmatrix.sync.aligned.m8n8.x4.shared.b16 {%0,%1,%2,%3}, [%4];"
        : "=r"(r[0]), "=r"(r[1]), "=r"(r[2]), "=r"(r[3]) : "r"(a));
}
__device__ __forceinline__ void ldsm4t(uint32_t* r, uint32_t a) {
    asm volatile("ldmatrix.sync.aligned.m8n8.x4.trans.shared.b16 {%0,%1,%2,%3}, [%4];"
        : "=r"(r[0]), "=r"(r[1]), "=r"(r[2]), "=r"(r[3]) : "r"(a));
}
__device__ __forceinline__ void mma16816(float* c, const uint32_t* a,
                                         uint32_t b0, uint32_t b1) {
    asm volatile(
        "mma.sync.aligned.m16n8k16.row.col.f32.bf16.bf16.f32 "
        "{%0,%1,%2,%3}, {%4,%5,%6,%7}, {%8,%9}, {%0,%1,%2,%3};"
        : "+f"(c[0]), "+f"(c[1]), "+f"(c[2]), "+f"(c[3])
        : "r"(a[0]), "r"(a[1]), "r"(a[2]), "r"(a[3]), "r"(b0), "r"(b1));
}

// grid barrier: all NCTA CTAs resident by construction
__device__ __forceinline__ void grid_bar() {
    __syncthreads();
    if (threadIdx.x == 0) {
        __threadfence();
        unsigned g = atomicAdd(&g_gen, 0u);
        if (atomicAdd(&g_cnt, 1u) == NCTA - 1) {
            g_cnt = 0;
            __threadfence();
            atomicAdd(&g_gen, 1u);
        } else {
            while (atomicAdd(&g_gen, 0u) == g) __nanosleep(64);
        }
    }
    __syncthreads();
}

// ---------------------------------------------------------------------------
// GEMM phase (R5 internals): part[feat][batch] = act[64,kchunk] @ W[kchunk,n128]
//   CTA tile n128 x m64, 8 warps (2m x 4n), warp m32 x n32
// ---------------------------------------------------------------------------
#define STAGE  49152
#define OFF_WH 0
#define OFF_WL 16384
#define OFF_AH 32768
#define OFF_AL 40960
#define GEMM_SMEM (2 * STAGE + 1024)

__device__ void gemm_phase(uint32_t s0,
                           const float* __restrict__ W, int N,
                           const __nv_bfloat16* __restrict__ actH,
                           const __nv_bfloat16* __restrict__ actL,
                           float* __restrict__ part,   // this split's base
                           int kb, int kchunk, int n0)
{
    const int tid = threadIdx.x;
    const int warp = tid >> 5, lane = tid & 31;
    const int warpM = warp & 1;
    const int warpN = warp >> 1;
    const int nst = kchunk >> 6;

    const int wk = tid >> 2;
    const int wn = (tid & 3) * 32;
    const float* wgp = W + (size_t)(kb + wk) * N + n0 + wn;
    const uint32_t wswz = (uint32_t)(wk & 7) << 4;
    const uint32_t wsrow = (uint32_t)wk * 256;

    const int am = tid >> 2;
    const int akb = (tid & 3) * 16;
    const __nv_bfloat16* agpH = actH + (size_t)am * DIM + kb + akb;
    const __nv_bfloat16* agpL = actL + (size_t)am * DIM + kb + akb;
    uint32_t aoffc[2];
    #pragma unroll
    for (int c = 0; c < 2; ++c)
        aoffc[c] = (uint32_t)am * 128
                 + (((uint32_t)(akb * 2 + c * 16)) ^ ((uint32_t)(am & 7) << 4));

    const uint32_t arow = (lane & 7) + ((lane >> 3) & 1) * 8;
    const uint32_t ak2  = ((lane >> 4) & 1) * 16;
    const uint32_t aswz = (uint32_t)(lane & 7) << 4;

    const uint32_t brow  = (lane & 7) + ((lane >> 3) & 1) * 8;
    const uint32_t bhalf = ((lane >> 4) & 1) * 8;

    float acc[2][4][4];
    #pragma unroll
    for (int i = 0; i < 2; ++i)
        #pragma unroll
        for (int j = 0; j < 4; ++j)
            #pragma unroll
            for (int q = 0; q < 4; ++q) acc[i][j][q] = 0.f;

    float4 wreg[8];

    auto loadW = [&](int s) {
        const float* p = wgp + (size_t)s * 64 * N;
        #pragma unroll
        for (int j = 0; j < 8; ++j) {
            int col = n0 + wn + j * 4;
            if (col + 3 < N) {
                wreg[j] = *reinterpret_cast<const float4*>(p + j * 4);
            } else {
                float4 v;
                v.x = (col + 0 < N) ? p[j * 4 + 0] : 0.f;
                v.y = (col + 1 < N) ? p[j * 4 + 1] : 0.f;
                v.z = (col + 2 < N) ? p[j * 4 + 2] : 0.f;
                v.w = (col + 3 < N) ? p[j * 4 + 3] : 0.f;
                wreg[j] = v;
            }
        }
    };
    auto storeW = [&](int buf) {
        const uint32_t base = s0 + buf * STAGE + wsrow;
        #pragma unroll
        for (int j = 0; j < 8; ++j) {
            uint32_t off = ((uint32_t)((wn + j * 4) * 2)) ^ wswz;
            float4 f = wreg[j];
            uint32_t h01, h23, l01, l23;
            asm("cvt.rn.satfinite.bf16x2.f32 %0, %1, %2;" : "=r"(h01) : "f"(f.y), "f"(f.x));
            asm("cvt.rn.satfinite.bf16x2.f32 %0, %1, %2;" : "=r"(h23) : "f"(f.w), "f"(f.z));
            float l0 = f.x - __uint_as_float(h01 << 16);
            float l1 = f.y - __uint_as_float(h01 & 0xffff0000u);
            float l2 = f.z - __uint_as_float(h23 << 16);
            float l3 = f.w - __uint_as_float(h23 & 0xffff0000u);
            asm("cvt.rn.satfinite.bf16x2.f32 %0, %1, %2;" : "=r"(l01) : "f"(l1), "f"(l0));
            asm("cvt.rn.satfinite.bf16x2.f32 %0, %1, %2;" : "=r"(l23) : "f"(l3), "f"(l2));
            asm volatile("st.shared.v2.b32 [%0], {%1,%2};"
                         :: "r"(base + OFF_WH + off), "r"(h01), "r"(h23));
            asm volatile("st.shared.v2.b32 [%0], {%1,%2};"
                         :: "r"(base + OFF_WL + off), "r"(l01), "r"(l23));
        }
    };
    auto issueA = [&](int s, int buf) {
        const uint32_t base = s0 + buf * STAGE;
        #pragma unroll
        for (int c = 0; c < 2; ++c) {
            cp16(base + OFF_AH + aoffc[c], agpH + s * 64 + c * 8);
            cp16(base + OFF_AL + aoffc[c], agpL + s * 64 + c * 8);
        }
        cp_commit();
    };
    auto compute = [&](int buf) {
        const uint32_t base = s0 + buf * STAGE;
        #pragma unroll
        for (int ks = 0; ks < 4; ++ks) {
            uint32_t bh[2][4], bl[2][4];
            #pragma unroll
            for (int nt = 0; nt < 2; ++nt) {
                uint32_t bcol = ((uint32_t)((warpN * 32 + nt * 16 + bhalf) * 2))
                              ^ ((uint32_t)(lane & 7) << 4);
                uint32_t boff = (uint32_t)(ks * 16 + brow) * 256 + bcol;
                ldsm4t(bh[nt], base + OFF_WH + boff);
                ldsm4t(bl[nt], base + OFF_WL + boff);
            }
            const uint32_t kx = (uint32_t)(ks * 32 + ak2) ^ aswz;
            #pragma unroll
            for (int mt = 0; mt < 2; ++mt) {
                const uint32_t arow0 = (uint32_t)(warpM * 32 + mt * 16) * 128
                                     + arow * 128 + kx;
                uint32_t ah[4], al[4];
                ldsm4(ah, base + OFF_AH + arow0);
                ldsm4(al, base + OFF_AL + arow0);
                #pragma unroll
                for (int nt = 0; nt < 2; ++nt) {
                    mma16816(acc[mt][nt * 2 + 0], ah, bh[nt][0], bh[nt][1]);
                    mma16816(acc[mt][nt * 2 + 1], ah, bh[nt][2], bh[nt][3]);
                    mma16816(acc[mt][nt * 2 + 0], al, bh[nt][0], bh[nt][1]);
                    mma16816(acc[mt][nt * 2 + 1], al, bh[nt][2], bh[nt][3]);
                    mma16816(acc[mt][nt * 2 + 0], ah, bl[nt][0], bl[nt][1]);
                    mma16816(acc[mt][nt * 2 + 1], ah, bl[nt][2], bl[nt][3]);
                }
            }
        }
    };

    issueA(0, 0);
    loadW(0);
    for (int s = 0; s < nst; ++s) {
        const int buf = s & 1;
        storeW(buf);
        if (s + 1 < nst) {
            issueA(s + 1, buf ^ 1);
            loadW(s + 1);
            cp_wait<1>();
        } else {
            cp_wait<0>();
        }
        __syncthreads();
        compute(buf);
        __syncthreads();
    }

    const int g = lane >> 2, tg = lane & 3;
    #pragma unroll
    for (int mt = 0; mt < 2; ++mt)
        #pragma unroll
        for (int nt = 0; nt < 4; ++nt) {
            int feat = n0 + warpN * 32 + nt * 8 + tg * 2;
            int bat  = warpM * 32 + mt * 16 + g;
            float* p = part + (size_t)feat * 64 + bat;
            p[0]      = acc[mt][nt][0];
            p[64]     = acc[mt][nt][1];
            p[8]      = acc[mt][nt][2];
            p[64 + 8] = acc[mt][nt][3];
        }
}

// ---------------------------------------------------------------------------
// fused persistent kernel
// ---------------------------------------------------------------------------
__global__ void __launch_bounds__(256, 2) fused_kernel(
    const float* __restrict__ x,
    const float* __restrict__ xa,
    const int*   __restrict__ lens,
    const float* __restrict__ w1, const float* __restrict__ b1,
    const float* __restrict__ w2, const float* __restrict__ b2,
    const float* __restrict__ w3, const float* __restrict__ b3,
    float* __restrict__ out)
{
    extern __shared__ char smraw[];
    const uint32_t s0 = (smem_u32(smraw) + 1023) & ~1023u;
    const int tid = threadIdx.x;
    const int bid = blockIdx.x;

    // ---------- phase 0: ragged max-pool -> bf16 hi/lo ----------
    {
        int gw = (bid * 256 + tid) >> 5;       // 0..2047
        int lane = tid & 31;
        for (int r = gw; r < BATCH * DIM; r += (NCTA * 256) / 32) {
            int b = r >> 12;
            int d = r & 4095;
            const float* src = (d < 2048)
                ? (x  + ((size_t)(b * 2048 + d)        ) * VIEWS)
                : (xa + ((size_t)(b * 2048 + (d - 2048))) * VIEWS);
            int len = lens[b];
            len = max(1, min(len, VIEWS));
            float m = -FLT_MAX;
            for (int v0 = lane * 4; v0 < len; v0 += 128) {
                float4 v = *reinterpret_cast<const float4*>(src + v0);
                m = fmaxf(m, v.x);
                if (v0 + 1 < len) m = fmaxf(m, v.y);
                if (v0 + 2 < len) m = fmaxf(m, v.z);
                if (v0 + 3 < len) m = fmaxf(m, v.w);
            }
            #pragma unroll
            for (int o = 16; o; o >>= 1)
                m = fmaxf(m, __shfl_xor_sync(0xffffffffu, m, o));
            if (lane == 0) {
                __nv_bfloat16 h = __float2bfloat16(m);
                g_actH[r] = h;
                g_actL[r] = __float2bfloat16(m - __bfloat162float(h));
            }
        }
    }
    grid_bar();

    // ---------- layer 1 + 2 ----------
    #pragma unroll 1
    for (int layer = 0; layer < 2; ++layer) {
        const float* W  = layer ? w2 : w1;
        const float* bs = layer ? b2 : b1;

        {   // gemm: 32 n-tiles x 8 k-splits = 256 CTAs
            const int n0 = (bid & 31) * 128;
            const int ks = bid >> 5;
            gemm_phase(s0, W, DIM, g_actH, g_actL,
                       g_part[ks], ks * 512, 512, n0);
        }
        grid_bar();

        {   // reduce + bias + relu -> act hi/lo
            for (int idx = bid * 256 + tid; idx < BATCH * DIM; idx += NCTA * 256) {
                int n = idx >> 12;
                int m = idx & 4095;
                float s = bs[m];
                #pragma unroll
                for (int z = 0; z < 8; ++z)
                    s += __ldcg(&g_part[z][m * 64 + n]);
                s = fmaxf(s, 0.f);
                __nv_bfloat16 h = __float2bfloat16(s);
                g_actH[idx] = h;
                g_actL[idx] = __float2bfloat16(s - __bfloat162float(h));
            }
        }
        grid_bar();
    }

    // ---------- layer 3: N=1000, 8 n-tiles x 16 k-splits = 128 CTAs ----------
    if (bid < 128) {
        const int n0 = (bid & 7) * 128;
        const int ks = bid >> 3;
        gemm_phase(s0, w3, OUTN, g_actH, g_actL,
                   g_part[ks], ks * 256, 256, n0);
    }
    grid_bar();

    {   // out = sum parts + b3
        for (int idx = bid * 256 + tid; idx < BATCH * OUTN; idx += NCTA * 256) {
            int n = idx / OUTN;
            int m = idx - n * OUTN;
            float s = b3[m];
            #pragma unroll
            for (int z = 0; z < 16; ++z)
                s += __ldcg(&g_part[z][m * 64 + n]);
            out[idx] = s;
        }
    }
}

// ---------------------------------------------------------------------------
// launch
// ---------------------------------------------------------------------------
extern "C" void kernel_launch(void* const* d_in, const int* in_sizes, int n_in,
                              void* d_out, int out_size)
{
    const float* x    = (const float*)d_in[0];
    const float* xa   = (const float*)d_in[1];
    const int*   lens = (const int*)  d_in[2];
    const float* w1   = (const float*)d_in[3];
    const float* b1   = (const float*)d_in[4];
    const float* w2   = (const float*)d_in[5];
    const float* b2   = (const float*)d_in[6];
    const float* w3   = (const float*)d_in[7];
    const float* b3   = (const float*)d_in[8];
    float* out = (float*)d_out;

    cudaFuncSetAttribute(fused_kernel,
                         cudaFuncAttributeMaxDynamicSharedMemorySize, GEMM_SMEM);

    fused_kernel<<<NCTA, 256, GEMM_SMEM>>>(x, xa, lens, w1, b1, w2, b2,
                                           w3, b3, out);
}

// round 7
// speedup vs baseline: 1.2575x; 1.2575x over previous
#include <cuda_runtime.h>
#include <cuda_bf16.h>
#include <float.h>
#include <stdint.h>

// ---------------------------------------------------------------------------
// MVCNN: ragged max-pool -> 3-layer MLP.
// GEMM: mma.sync.m16n8k16 bf16 hi/lo (3 MMAs), f32 acc (R5-proven core).
// R7: reduce fused into GEMM via per-tile completion counters (last ksplit
//     CTA reduces); partials [batch][feat] for coalesced reduce; act double-
//     buffered. 4 kernel launches total.
// ---------------------------------------------------------------------------

#define BATCH 64
#define DIM   4096
#define VIEWS 256
#define OUTN  1000

__device__ __align__(256) __nv_bfloat16 g_actH0[BATCH * DIM];
__device__ __align__(256) __nv_bfloat16 g_actL0[BATCH * DIM];
__device__ __align__(256) __nv_bfloat16 g_actH1[BATCH * DIM];
__device__ __align__(256) __nv_bfloat16 g_actL1[BATCH * DIM];
__device__ __align__(256) float g_part[16][BATCH * DIM];  // [ksplit][batch][feat]
__device__ unsigned g_cntA[32];
__device__ unsigned g_cntB[32];
__device__ unsigned g_cntC[8];

// ---------------------------------------------------------------------------
// helpers
// ---------------------------------------------------------------------------
__device__ __forceinline__ uint32_t smem_u32(const void* p) {
    uint32_t a;
    asm("{ .reg .u64 t; cvta.to.shared.u64 t, %1; cvt.u32.u64 %0, t; }"
        : "=r"(a) : "l"(p));
    return a;
}
__device__ __forceinline__ void cp16(uint32_t dst, const void* src) {
    asm volatile("cp.async.cg.shared.global [%0], [%1], 16;"
                 :: "r"(dst), "l"(src));
}
__device__ __forceinline__ void cp_commit() {
    asm volatile("cp.async.commit_group;" ::: "memory");
}
template<int N> __device__ __forceinline__ void cp_wait() {
    asm volatile("cp.async.wait_group %0;" :: "n"(N) : "memory");
}
__device__ __forceinline__ void ldsm4(uint32_t* r, uint32_t a) {
    asm volatile("ldmatrix.sync.aligned.m8n8.x4.shared.b16 {%0,%1,%2,%3}, [%4];"
        : "=r"(r[0]), "=r"(r[1]), "=r"(r[2]), "=r"(r[3]) : "r"(a));
}
__device__ __forceinline__ void ldsm4t(uint32_t* r, uint32_t a) {
    asm volatile("ldmatrix.sync.aligned.m8n8.x4.trans.shared.b16 {%0,%1,%2,%3}, [%4];"
        : "=r"(r[0]), "=r"(r[1]), "=r"(r[2]), "=r"(r[3]) : "r"(a));
}
__device__ __forceinline__ void mma16816(float* c, const uint32_t* a,
                                         uint32_t b0, uint32_t b1) {
    asm volatile(
        "mma.sync.aligned.m16n8k16.row.col.f32.bf16.bf16.f32 "
        "{%0,%1,%2,%3}, {%4,%5,%6,%7}, {%8,%9}, {%0,%1,%2,%3};"
        : "+f"(c[0]), "+f"(c[1]), "+f"(c[2]), "+f"(c[3])
        : "r"(a[0]), "r"(a[1]), "r"(a[2]), "r"(a[3]), "r"(b0), "r"(b1));
}

// ---------------------------------------------------------------------------
// Ragged max-pool -> bf16 hi/lo activations  act[batch][feat]
// ---------------------------------------------------------------------------
__global__ void pool_kernel(const float* __restrict__ x,
                            const float* __restrict__ xa,
                            const int*   __restrict__ lens,
                            __nv_bfloat16* __restrict__ actH,
                            __nv_bfloat16* __restrict__ actL)
{
    int warp = (blockIdx.x * blockDim.x + threadIdx.x) >> 5;
    int lane = threadIdx.x & 31;
    if (warp >= BATCH * DIM) return;
    int b = warp >> 12;
    int d = warp & 4095;

    const float* src = (d < 2048)
        ? (x  + ((size_t)(b * 2048 + d)        ) * VIEWS)
        : (xa + ((size_t)(b * 2048 + (d - 2048))) * VIEWS);

    int len = lens[b];
    len = max(1, min(len, VIEWS));

    float m = -FLT_MAX;
    for (int v0 = lane * 4; v0 < len; v0 += 128) {
        float4 v = *reinterpret_cast<const float4*>(src + v0);
        m = fmaxf(m, v.x);
        if (v0 + 1 < len) m = fmaxf(m, v.y);
        if (v0 + 2 < len) m = fmaxf(m, v.z);
        if (v0 + 3 < len) m = fmaxf(m, v.w);
    }
    #pragma unroll
    for (int o = 16; o; o >>= 1)
        m = fmaxf(m, __shfl_xor_sync(0xffffffffu, m, o));

    if (lane == 0) {
        __nv_bfloat16 h = __float2bfloat16(m);
        actH[warp] = h;
        actL[warp] = __float2bfloat16(m - __bfloat162float(h));
    }
}

// ---------------------------------------------------------------------------
// GEMM + fused reduce.
//   grid (ntiles, KS), 256 thr = 8 warps (2m x 4n), warp m32 x n32
//   partials: g_part[ks][bat][feat]
//   Last ksplit CTA per n-tile reduces: +bias (+relu -> bf16 hi/lo) or -> out.
// ---------------------------------------------------------------------------
#define STAGE  49152
#define OFF_WH 0
#define OFF_WL 16384
#define OFF_AH 32768
#define OFF_AL 40960
#define GEMM_SMEM (2 * STAGE + 1024)

template<int KS, bool FINAL>
__global__ void __launch_bounds__(256) gemm_fused(
    const float* __restrict__ W, int N,
    const __nv_bfloat16* __restrict__ actH,
    const __nv_bfloat16* __restrict__ actL,
    const float* __restrict__ bias,
    __nv_bfloat16* __restrict__ outH,
    __nv_bfloat16* __restrict__ outL,
    float* __restrict__ outF,
    unsigned* __restrict__ cnt,
    int kchunk)
{
    extern __shared__ char smraw[];
    const uint32_t s0 = (smem_u32(smraw) + 1023) & ~1023u;
    const int tid = threadIdx.x;
    const int warp = tid >> 5, lane = tid & 31;
    const int warpM = warp & 1;
    const int warpN = warp >> 1;
    const int n0 = blockIdx.x * 128;
    const int kb = blockIdx.y * kchunk;
    float* part = g_part[blockIdx.y];
    const int nst = kchunk >> 6;

    const int wk = tid >> 2;
    const int wn = (tid & 3) * 32;
    const float* wgp = W + (size_t)(kb + wk) * N + n0 + wn;
    const uint32_t wswz = (uint32_t)(wk & 7) << 4;
    const uint32_t wsrow = (uint32_t)wk * 256;

    const int am = tid >> 2;
    const int akb = (tid & 3) * 16;
    const __nv_bfloat16* agpH = actH + (size_t)am * DIM + kb + akb;
    const __nv_bfloat16* agpL = actL + (size_t)am * DIM + kb + akb;
    uint32_t aoffc[2];
    #pragma unroll
    for (int c = 0; c < 2; ++c)
        aoffc[c] = (uint32_t)am * 128
                 + (((uint32_t)(akb * 2 + c * 16)) ^ ((uint32_t)(am & 7) << 4));

    const uint32_t arow = (lane & 7) + ((lane >> 3) & 1) * 8;
    const uint32_t ak2  = ((lane >> 4) & 1) * 16;
    const uint32_t aswz = (uint32_t)(lane & 7) << 4;

    const uint32_t brow  = (lane & 7) + ((lane >> 3) & 1) * 8;
    const uint32_t bhalf = ((lane >> 4) & 1) * 8;

    float acc[2][4][4];
    #pragma unroll
    for (int i = 0; i < 2; ++i)
        #pragma unroll
        for (int j = 0; j < 4; ++j)
            #pragma unroll
            for (int q = 0; q < 4; ++q) acc[i][j][q] = 0.f;

    float4 wreg[8];

    auto loadW = [&](int s) {
        const float* p = wgp + (size_t)s * 64 * N;
        #pragma unroll
        for (int j = 0; j < 8; ++j) {
            int col = n0 + wn + j * 4;
            if (col + 3 < N) {
                wreg[j] = *reinterpret_cast<const float4*>(p + j * 4);
            } else {
                float4 v;
                v.x = (col + 0 < N) ? p[j * 4 + 0] : 0.f;
                v.y = (col + 1 < N) ? p[j * 4 + 1] : 0.f;
                v.z = (col + 2 < N) ? p[j * 4 + 2] : 0.f;
                v.w = (col + 3 < N) ? p[j * 4 + 3] : 0.f;
                wreg[j] = v;
            }
        }
    };
    auto storeW = [&](int buf) {
        const uint32_t base = s0 + buf * STAGE + wsrow;
        #pragma unroll
        for (int j = 0; j < 8; ++j) {
            uint32_t off = ((uint32_t)((wn + j * 4) * 2)) ^ wswz;
            float4 f = wreg[j];
            uint32_t h01, h23, l01, l23;
            asm("cvt.rn.satfinite.bf16x2.f32 %0, %1, %2;" : "=r"(h01) : "f"(f.y), "f"(f.x));
            asm("cvt.rn.satfinite.bf16x2.f32 %0, %1, %2;" : "=r"(h23) : "f"(f.w), "f"(f.z));
            float l0 = f.x - __uint_as_float(h01 << 16);
            float l1 = f.y - __uint_as_float(h01 & 0xffff0000u);
            float l2 = f.z - __uint_as_float(h23 << 16);
            float l3 = f.w - __uint_as_float(h23 & 0xffff0000u);
            asm("cvt.rn.satfinite.bf16x2.f32 %0, %1, %2;" : "=r"(l01) : "f"(l1), "f"(l0));
            asm("cvt.rn.satfinite.bf16x2.f32 %0, %1, %2;" : "=r"(l23) : "f"(l3), "f"(l2));
            asm volatile("st.shared.v2.b32 [%0], {%1,%2};"
                         :: "r"(base + OFF_WH + off), "r"(h01), "r"(h23));
            asm volatile("st.shared.v2.b32 [%0], {%1,%2};"
                         :: "r"(base + OFF_WL + off), "r"(l01), "r"(l23));
        }
    };
    auto issueA = [&](int s, int buf) {
        const uint32_t base = s0 + buf * STAGE;
        #pragma unroll
        for (int c = 0; c < 2; ++c) {
            cp16(base + OFF_AH + aoffc[c], agpH + s * 64 + c * 8);
            cp16(base + OFF_AL + aoffc[c], agpL + s * 64 + c * 8);
        }
        cp_commit();
    };
    auto compute = [&](int buf) {
        const uint32_t base = s0 + buf * STAGE;
        #pragma unroll
        for (int ks = 0; ks < 4; ++ks) {
            uint32_t bh[2][4], bl[2][4];
            #pragma unroll
            for (int nt = 0; nt < 2; ++nt) {
                uint32_t bcol = ((uint32_t)((warpN * 32 + nt * 16 + bhalf) * 2))
                              ^ ((uint32_t)(lane & 7) << 4);
                uint32_t boff = (uint32_t)(ks * 16 + brow) * 256 + bcol;
                ldsm4t(bh[nt], base + OFF_WH + boff);
                ldsm4t(bl[nt], base + OFF_WL + boff);
            }
            const uint32_t kx = (uint32_t)(ks * 32 + ak2) ^ aswz;
            #pragma unroll
            for (int mt = 0; mt < 2; ++mt) {
                const uint32_t arow0 = (uint32_t)(warpM * 32 + mt * 16) * 128
                                     + arow * 128 + kx;
                uint32_t ah[4], al[4];
                ldsm4(ah, base + OFF_AH + arow0);
                ldsm4(al, base + OFF_AL + arow0);
                #pragma unroll
                for (int nt = 0; nt < 2; ++nt) {
                    mma16816(acc[mt][nt * 2 + 0], ah, bh[nt][0], bh[nt][1]);
                    mma16816(acc[mt][nt * 2 + 1], ah, bh[nt][2], bh[nt][3]);
                    mma16816(acc[mt][nt * 2 + 0], al, bh[nt][0], bh[nt][1]);
                    mma16816(acc[mt][nt * 2 + 1], al, bh[nt][2], bh[nt][3]);
                    mma16816(acc[mt][nt * 2 + 0], ah, bl[nt][0], bl[nt][1]);
                    mma16816(acc[mt][nt * 2 + 1], ah, bl[nt][2], bl[nt][3]);
                }
            }
        }
    };

    // ---- R5-proven pipeline ----
    issueA(0, 0);
    loadW(0);
    for (int s = 0; s < nst; ++s) {
        const int buf = s & 1;
        storeW(buf);
        if (s + 1 < nst) {
            issueA(s + 1, buf ^ 1);
            loadW(s + 1);
            cp_wait<1>();
        } else {
            cp_wait<0>();
        }
        __syncthreads();
        compute(buf);
        __syncthreads();
    }

    // ---- epilogue: partials [bat][feat], float2 stores ----
    const int g = lane >> 2, tg = lane & 3;
    #pragma unroll
    for (int mt = 0; mt < 2; ++mt)
        #pragma unroll
        for (int nt = 0; nt < 4; ++nt) {
            int feat = n0 + warpN * 32 + nt * 8 + tg * 2;
            int bat  = warpM * 32 + mt * 16 + g;
            float* p = part + (size_t)bat * DIM + feat;
            float2 v0 = make_float2(acc[mt][nt][0], acc[mt][nt][1]);
            float2 v1 = make_float2(acc[mt][nt][2], acc[mt][nt][3]);
            *reinterpret_cast<float2*>(p)           = v0;
            *reinterpret_cast<float2*>(p + 8 * DIM) = v1;
        }

    // ---- completion counter: last ksplit CTA of this n-tile reduces ----
    __threadfence();
    __shared__ unsigned s_last;
    if (tid == 0) s_last = atomicAdd(&cnt[blockIdx.x], 1u);
    __syncthreads();
    if (s_last != KS - 1) return;
    if (tid == 0) cnt[blockIdx.x] = 0;   // self-reset for graph replay
    __threadfence();

    if (!FINAL) {
        // feats n0..n0+127, all batches: + bias, relu, bf16 hi/lo
        for (int idx = tid; idx < 128 * BATCH; idx += 256) {
            int m = n0 + (idx & 127);
            int n = idx >> 7;
            float s = bias[m];
            #pragma unroll
            for (int z = 0; z < KS; ++z)
                s += __ldcg(&g_part[z][(size_t)n * DIM + m]);
            s = fmaxf(s, 0.f);
            __nv_bfloat16 h = __float2bfloat16(s);
            outH[(size_t)n * DIM + m] = h;
            outL[(size_t)n * DIM + m] = __float2bfloat16(s - __bfloat162float(h));
        }
    } else {
        for (int idx = tid; idx < 128 * BATCH; idx += 256) {
            int m = n0 + (idx & 127);
            if (m >= N) continue;
            int n = idx >> 7;
            float s = bias[m];
            #pragma unroll
            for (int z = 0; z < KS; ++z)
                s += __ldcg(&g_part[z][(size_t)n * DIM + m]);
            outF[(size_t)n * N + m] = s;
        }
    }
}

// ---------------------------------------------------------------------------
// launch
// ---------------------------------------------------------------------------
extern "C" void kernel_launch(void* const* d_in, const int* in_sizes, int n_in,
                              void* d_out, int out_size)
{
    const float* x    = (const float*)d_in[0];
    const float* xa   = (const float*)d_in[1];
    const int*   lens = (const int*)  d_in[2];
    const float* w1   = (const float*)d_in[3];
    const float* b1   = (const float*)d_in[4];
    const float* w2   = (const float*)d_in[5];
    const float* b2   = (const float*)d_in[6];
    const float* w3   = (const float*)d_in[7];
    const float* b3   = (const float*)d_in[8];
    float* out = (float*)d_out;

    __nv_bfloat16 *aH0, *aL0, *aH1, *aL1;
    unsigned *cA, *cB, *cC;
    cudaGetSymbolAddress((void**)&aH0, g_actH0);
    cudaGetSymbolAddress((void**)&aL0, g_actL0);
    cudaGetSymbolAddress((void**)&aH1, g_actH1);
    cudaGetSymbolAddress((void**)&aL1, g_actL1);
    cudaGetSymbolAddress((void**)&cA, g_cntA);
    cudaGetSymbolAddress((void**)&cB, g_cntB);
    cudaGetSymbolAddress((void**)&cC, g_cntC);

    cudaFuncSetAttribute(gemm_fused<8, false>,
                         cudaFuncAttributeMaxDynamicSharedMemorySize, GEMM_SMEM);
    cudaFuncSetAttribute(gemm_fused<16, true>,
                         cudaFuncAttributeMaxDynamicSharedMemorySize, GEMM_SMEM);

    // 1) pool -> act0 hi/lo
    {
        int warps = BATCH * DIM;
        int blocks = (warps * 32 + 255) / 256;
        pool_kernel<<<blocks, 256>>>(x, xa, lens, aH0, aL0);
    }
    // 2) layer 1: act0 -> act1
    gemm_fused<8, false><<<dim3(32, 8), 256, GEMM_SMEM>>>(
        w1, DIM, aH0, aL0, b1, aH1, aL1, nullptr, cA, 512);
    // 3) layer 2: act1 -> act0
    gemm_fused<8, false><<<dim3(32, 8), 256, GEMM_SMEM>>>(
        w2, DIM, aH1, aL1, b2, aH0, aL0, nullptr, cB, 512);
    // 4) layer 3: act0 -> out
    gemm_fused<16, true><<<dim3(8, 16), 256, GEMM_SMEM>>>(
        w3, OUTN, aH0, aL0, b3, nullptr, nullptr, out, cC, 256);
}

// round 8
// speedup vs baseline: 1.5453x; 1.2289x over previous
#include <cuda_runtime.h>
#include <cuda_bf16.h>
#include <float.h>
#include <stdint.h>

// ---------------------------------------------------------------------------
// MVCNN: ragged max-pool -> 3-layer MLP.
// GEMMs via mma.sync.m16n8k16 (bf16 hi/lo split, f32 acc), sm_80-portable ISA.
//   C[64, N] = act[64, 4096] @ W[4096, N]
//   3 MMAs per k-step: Ah*Wh + Al*Wh + Ah*Wl  (rel err ~2^-16)
// R8 = R5 (proven 149.4us) + layer-3 ksplit 16 -> 32 (256 CTAs, 2/SM).
// ---------------------------------------------------------------------------

#define BATCH 64
#define DIM   4096
#define VIEWS 256
#define OUTN  1000

__device__ __align__(256) __nv_bfloat16 g_actH[BATCH * DIM];
__device__ __align__(256) __nv_bfloat16 g_actL[BATCH * DIM];
__device__ __align__(256) float g_part[32][DIM * BATCH];  // [ksplit][feat][batch]

// ---------------------------------------------------------------------------
// helpers
// ---------------------------------------------------------------------------
__device__ __forceinline__ uint32_t smem_u32(const void* p) {
    uint32_t a;
    asm("{ .reg .u64 t; cvta.to.shared.u64 t, %1; cvt.u32.u64 %0, t; }"
        : "=r"(a) : "l"(p));
    return a;
}
__device__ __forceinline__ void cp16(uint32_t dst, const void* src) {
    asm volatile("cp.async.cg.shared.global [%0], [%1], 16;"
                 :: "r"(dst), "l"(src));
}
__device__ __forceinline__ void cp_commit() {
    asm volatile("cp.async.commit_group;" ::: "memory");
}
template<int N> __device__ __forceinline__ void cp_wait() {
    asm volatile("cp.async.wait_group %0;" :: "n"(N) : "memory");
}
__device__ __forceinline__ void ldsm4(uint32_t* r, uint32_t a) {
    asm volatile("ldmatrix.sync.aligned.m8n8.x4.shared.b16 {%0,%1,%2,%3}, [%4];"
        : "=r"(r[0]), "=r"(r[1]), "=r"(r[2]), "=r"(r[3]) : "r"(a));
}
__device__ __forceinline__ void ldsm4t(uint32_t* r, uint32_t a) {
    asm volatile("ldmatrix.sync.aligned.m8n8.x4.trans.shared.b16 {%0,%1,%2,%3}, [%4];"
        : "=r"(r[0]), "=r"(r[1]), "=r"(r[2]), "=r"(r[3]) : "r"(a));
}
__device__ __forceinline__ void mma16816(float* c, const uint32_t* a,
                                         uint32_t b0, uint32_t b1) {
    asm volatile(
        "mma.sync.aligned.m16n8k16.row.col.f32.bf16.bf16.f32 "
        "{%0,%1,%2,%3}, {%4,%5,%6,%7}, {%8,%9}, {%0,%1,%2,%3};"
        : "+f"(c[0]), "+f"(c[1]), "+f"(c[2]), "+f"(c[3])
        : "r"(a[0]), "r"(a[1]), "r"(a[2]), "r"(a[3]), "r"(b0), "r"(b1));
}

// ---------------------------------------------------------------------------
// Ragged max-pool -> bf16 hi/lo activations  act[batch][feat]
// ---------------------------------------------------------------------------
__global__ void pool_kernel(const float* __restrict__ x,
                            const float* __restrict__ xa,
                            const int*   __restrict__ lens,
                            __nv_bfloat16* __restrict__ actH,
                            __nv_bfloat16* __restrict__ actL)
{
    int warp = (blockIdx.x * blockDim.x + threadIdx.x) >> 5;
    int lane = threadIdx.x & 31;
    if (warp >= BATCH * DIM) return;
    int b = warp >> 12;
    int d = warp & 4095;

    const float* src = (d < 2048)
        ? (x  + ((size_t)(b * 2048 + d)        ) * VIEWS)
        : (xa + ((size_t)(b * 2048 + (d - 2048))) * VIEWS);

    int len = lens[b];
    len = max(1, min(len, VIEWS));

    float m = -FLT_MAX;
    for (int v0 = lane * 4; v0 < len; v0 += 128) {
        float4 v = *reinterpret_cast<const float4*>(src + v0);
        m = fmaxf(m, v.x);
        if (v0 + 1 < len) m = fmaxf(m, v.y);
        if (v0 + 2 < len) m = fmaxf(m, v.z);
        if (v0 + 3 < len) m = fmaxf(m, v.w);
    }
    #pragma unroll
    for (int o = 16; o; o >>= 1)
        m = fmaxf(m, __shfl_xor_sync(0xffffffffu, m, o));

    if (lane == 0) {
        __nv_bfloat16 h = __float2bfloat16(m);
        actH[warp] = h;
        actL[warp] = __float2bfloat16(m - __bfloat162float(h));
    }
}

// ---------------------------------------------------------------------------
// GEMM: part[ks][feat][batch] = act[64, kchunk] @ W[kchunk, n128-tile]
//   grid (ceil(N/128), KSPLIT), 256 threads = 8 warps, warp tile m32 x n32
//   smem: 2 stages x { WH 16K (k64 x n128) | WL 16K | AH 8K | AL 8K }
// ---------------------------------------------------------------------------
#define STAGE  49152
#define OFF_WH 0
#define OFF_WL 16384
#define OFF_AH 32768
#define OFF_AL 40960
#define GEMM_SMEM (2 * STAGE + 1024)

__global__ void __launch_bounds__(256) gemm_mma(
    const float* __restrict__ W, int N,
    const __nv_bfloat16* __restrict__ actH,
    const __nv_bfloat16* __restrict__ actL,
    float* __restrict__ partBase, int kchunk)
{
    extern __shared__ char smraw[];
    const uint32_t s0 = (smem_u32(smraw) + 1023) & ~1023u;
    const int tid = threadIdx.x;
    const int warp = tid >> 5, lane = tid & 31;
    const int warpM = warp & 1;         // m32 slice of batch-64
    const int warpN = warp >> 1;        // n32 slice of 128
    const int n0 = blockIdx.x * 128;
    const int kb = blockIdx.y * kchunk;
    float* part = partBase + (size_t)blockIdx.y * (DIM * BATCH);
    const int nst = kchunk >> 6;

    // W fp32 load: thread -> k row (tid>>2), n quarter ((tid&3)*32); 8 float4
    const int wk = tid >> 2;
    const int wn = (tid & 3) * 32;
    const float* wgp = W + (size_t)(kb + wk) * N + n0 + wn;
    const uint32_t wswz = (uint32_t)(wk & 7) << 4;
    const uint32_t wsrow = (uint32_t)wk * 256;

    // A cp.async: thread -> m row (tid>>2), k chunk; 2 x 16B per polarity
    const int am = tid >> 2;
    const int akb = (tid & 3) * 16;                 // k elem offset
    const __nv_bfloat16* agpH = actH + (size_t)am * DIM + kb + akb;
    const __nv_bfloat16* agpL = actL + (size_t)am * DIM + kb + akb;
    uint32_t aoffc[2];
    #pragma unroll
    for (int c = 0; c < 2; ++c)
        aoffc[c] = (uint32_t)am * 128
                 + (((uint32_t)(akb * 2 + c * 16)) ^ ((uint32_t)(am & 7) << 4));

    // ldmatrix A: lane -> row within m16 tile, k-half
    const uint32_t arow = (lane & 7) + ((lane >> 3) & 1) * 8;
    const uint32_t ak2  = ((lane >> 4) & 1) * 16;   // byte offset (k8)
    const uint32_t aswz = (uint32_t)(lane & 7) << 4;

    // ldmatrix B trans on W smem [k][n128]: lane -> k row; n via warpN/nt
    const uint32_t brow  = (lane & 7) + ((lane >> 3) & 1) * 8;
    const uint32_t bhalf = ((lane >> 4) & 1) * 8;   // n elems

    float acc[2][4][4];
    #pragma unroll
    for (int i = 0; i < 2; ++i)
        #pragma unroll
        for (int j = 0; j < 4; ++j)
            #pragma unroll
            for (int q = 0; q < 4; ++q) acc[i][j][q] = 0.f;

    float4 wreg[8];

    auto loadW = [&](int s) {
        const float* p = wgp + (size_t)s * 64 * N;
        #pragma unroll
        for (int j = 0; j < 8; ++j) {
            int col = n0 + wn + j * 4;
            if (col + 3 < N) {
                wreg[j] = *reinterpret_cast<const float4*>(p + j * 4);
            } else {
                float4 v;
                v.x = (col + 0 < N) ? p[j * 4 + 0] : 0.f;
                v.y = (col + 1 < N) ? p[j * 4 + 1] : 0.f;
                v.z = (col + 2 < N) ? p[j * 4 + 2] : 0.f;
                v.w = (col + 3 < N) ? p[j * 4 + 3] : 0.f;
                wreg[j] = v;
            }
        }
    };
    auto storeW = [&](int buf) {
        const uint32_t base = s0 + buf * STAGE + wsrow;
        #pragma unroll
        for (int j = 0; j < 8; ++j) {
            uint32_t off = ((uint32_t)((wn + j * 4) * 2)) ^ wswz;
            float4 f = wreg[j];
            uint32_t h01, h23, l01, l23;
            asm("cvt.rn.satfinite.bf16x2.f32 %0, %1, %2;" : "=r"(h01) : "f"(f.y), "f"(f.x));
            asm("cvt.rn.satfinite.bf16x2.f32 %0, %1, %2;" : "=r"(h23) : "f"(f.w), "f"(f.z));
            float l0 = f.x - __uint_as_float(h01 << 16);
            float l1 = f.y - __uint_as_float(h01 & 0xffff0000u);
            float l2 = f.z - __uint_as_float(h23 << 16);
            float l3 = f.w - __uint_as_float(h23 & 0xffff0000u);
            asm("cvt.rn.satfinite.bf16x2.f32 %0, %1, %2;" : "=r"(l01) : "f"(l1), "f"(l0));
            asm("cvt.rn.satfinite.bf16x2.f32 %0, %1, %2;" : "=r"(l23) : "f"(l3), "f"(l2));
            asm volatile("st.shared.v2.b32 [%0], {%1,%2};"
                         :: "r"(base + OFF_WH + off), "r"(h01), "r"(h23));
            asm volatile("st.shared.v2.b32 [%0], {%1,%2};"
                         :: "r"(base + OFF_WL + off), "r"(l01), "r"(l23));
        }
    };
    auto issueA = [&](int s, int buf) {
        const uint32_t base = s0 + buf * STAGE;
        #pragma unroll
        for (int c = 0; c < 2; ++c) {
            cp16(base + OFF_AH + aoffc[c], agpH + s * 64 + c * 8);
            cp16(base + OFF_AL + aoffc[c], agpL + s * 64 + c * 8);
        }
        cp_commit();
    };
    auto compute = [&](int buf) {
        const uint32_t base = s0 + buf * STAGE;
        #pragma unroll
        for (int ks = 0; ks < 4; ++ks) {
            uint32_t bh[2][4], bl[2][4];
            #pragma unroll
            for (int nt = 0; nt < 2; ++nt) {
                uint32_t bcol = ((uint32_t)((warpN * 32 + nt * 16 + bhalf) * 2))
                              ^ ((uint32_t)(lane & 7) << 4);
                uint32_t boff = (uint32_t)(ks * 16 + brow) * 256 + bcol;
                ldsm4t(bh[nt], base + OFF_WH + boff);
                ldsm4t(bl[nt], base + OFF_WL + boff);
            }
            const uint32_t kx = (uint32_t)(ks * 32 + ak2) ^ aswz;
            #pragma unroll
            for (int mt = 0; mt < 2; ++mt) {
                const uint32_t arow0 = (uint32_t)(warpM * 32 + mt * 16) * 128
                                     + arow * 128 + kx;
                uint32_t ah[4], al[4];
                ldsm4(ah, base + OFF_AH + arow0);
                ldsm4(al, base + OFF_AL + arow0);
                #pragma unroll
                for (int nt = 0; nt < 2; ++nt) {
                    mma16816(acc[mt][nt * 2 + 0], ah, bh[nt][0], bh[nt][1]);
                    mma16816(acc[mt][nt * 2 + 1], ah, bh[nt][2], bh[nt][3]);
                    mma16816(acc[mt][nt * 2 + 0], al, bh[nt][0], bh[nt][1]);
                    mma16816(acc[mt][nt * 2 + 1], al, bh[nt][2], bh[nt][3]);
                    mma16816(acc[mt][nt * 2 + 0], ah, bl[nt][0], bl[nt][1]);
                    mma16816(acc[mt][nt * 2 + 1], ah, bl[nt][2], bl[nt][3]);
                }
            }
        }
    };

    // ---- R3/R5-proven pipeline ordering ----
    issueA(0, 0);
    loadW(0);
    for (int s = 0; s < nst; ++s) {
        const int buf = s & 1;
        storeW(buf);
        if (s + 1 < nst) {
            issueA(s + 1, buf ^ 1);
            loadW(s + 1);
            cp_wait<1>();
        } else {
            cp_wait<0>();
        }
        __syncthreads();
        compute(buf);
        __syncthreads();
    }

    // epilogue: scatter f32 partials  part[feat*64 + batch]
    const int g = lane >> 2, tg = lane & 3;
    #pragma unroll
    for (int mt = 0; mt < 2; ++mt)
        #pragma unroll
        for (int nt = 0; nt < 4; ++nt) {
            int feat = n0 + warpN * 32 + nt * 8 + tg * 2;
            int bat  = warpM * 32 + mt * 16 + g;
            float* p = part + (size_t)feat * 64 + bat;
            p[0]      = acc[mt][nt][0];
            p[64]     = acc[mt][nt][1];
            p[8]      = acc[mt][nt][2];
            p[64 + 8] = acc[mt][nt][3];
        }
}

// ---------------------------------------------------------------------------
// Reduce K-splits + bias + relu -> next-layer bf16 hi/lo activations
// ---------------------------------------------------------------------------
__global__ void reduce_bias_relu(const float* __restrict__ bias,
                                 __nv_bfloat16* __restrict__ actH,
                                 __nv_bfloat16* __restrict__ actL)
{
    int idx = blockIdx.x * 256 + threadIdx.x;   // 64*4096
    int n = idx >> 12;       // batch
    int m = idx & 4095;      // feat
    float s = bias[m];
    #pragma unroll
    for (int z = 0; z < 8; ++z) s += g_part[z][m * 64 + n];
    s = fmaxf(s, 0.f);
    __nv_bfloat16 h = __float2bfloat16(s);
    actH[idx] = h;
    actL[idx] = __float2bfloat16(s - __bfloat162float(h));
}

__global__ void reduce_out(const float* __restrict__ b3,
                           float* __restrict__ out)
{
    int idx = blockIdx.x * 256 + threadIdx.x;
    if (idx >= BATCH * OUTN) return;
    int n = idx / OUTN;      // batch
    int m = idx - n * OUTN;  // feat
    float s = b3[m];
    #pragma unroll
    for (int z = 0; z < 32; ++z) s += g_part[z][m * 64 + n];
    out[idx] = s;
}

// ---------------------------------------------------------------------------
// launch
// ---------------------------------------------------------------------------
extern "C" void kernel_launch(void* const* d_in, const int* in_sizes, int n_in,
                              void* d_out, int out_size)
{
    const float* x    = (const float*)d_in[0];
    const float* xa   = (const float*)d_in[1];
    const int*   lens = (const int*)  d_in[2];
    const float* w1   = (const float*)d_in[3];
    const float* b1   = (const float*)d_in[4];
    const float* w2   = (const float*)d_in[5];
    const float* b2   = (const float*)d_in[6];
    const float* w3   = (const float*)d_in[7];
    const float* b3   = (const float*)d_in[8];
    float* out = (float*)d_out;

    __nv_bfloat16 *actH, *actL;
    float* part;
    cudaGetSymbolAddress((void**)&actH, g_actH);
    cudaGetSymbolAddress((void**)&actL, g_actL);
    cudaGetSymbolAddress((void**)&part, g_part);

    cudaFuncSetAttribute(gemm_mma, cudaFuncAttributeMaxDynamicSharedMemorySize,
                         GEMM_SMEM);

    // 1) pool -> act hi/lo
    {
        int warps = BATCH * DIM;
        int blocks = (warps * 32 + 255) / 256;
        pool_kernel<<<blocks, 256>>>(x, xa, lens, actH, actL);
    }
    // 2) layer 1: n-tiles 32, ksplit 8 (kchunk 512, 8 stages)
    gemm_mma<<<dim3(32, 8), 256, GEMM_SMEM>>>(w1, DIM, actH, actL, part, 512);
    reduce_bias_relu<<<1024, 256>>>(b1, actH, actL);
    // 3) layer 2
    gemm_mma<<<dim3(32, 8), 256, GEMM_SMEM>>>(w2, DIM, actH, actL, part, 512);
    reduce_bias_relu<<<1024, 256>>>(b2, actH, actL);
    // 4) layer 3: N=1000 -> 8 n-tiles, ksplit 32 (kchunk 128, 2 stages)
    gemm_mma<<<dim3(8, 32), 256, GEMM_SMEM>>>(w3, OUTN, actH, actL, part, 128);
    reduce_out<<<(BATCH * OUTN + 255) / 256, 256>>>(b3, out);
}

// round 9
// speedup vs baseline: 1.5910x; 1.0295x over previous
#include <cuda_runtime.h>
#include <cuda_bf16.h>
#include <float.h>
#include <stdint.h>

// ---------------------------------------------------------------------------
// MVCNN: ragged max-pool -> 3-layer MLP.
// GEMMs via mma.sync.m16n8k16 (bf16 hi/lo split, f32 acc).
// R9: single-barrier stage loop (issueA moved after sync -> post-compute
//     sync provably removable); templated n-tile (128 for L1/2, 64 for L3).
// ---------------------------------------------------------------------------

#define BATCH 64
#define DIM   4096
#define VIEWS 256
#define OUTN  1000

__device__ __align__(256) __nv_bfloat16 g_actH[BATCH * DIM];
__device__ __align__(256) __nv_bfloat16 g_actL[BATCH * DIM];
__device__ __align__(256) float g_part[16][DIM * BATCH];  // [ksplit][feat][batch]

// ---------------------------------------------------------------------------
// helpers
// ---------------------------------------------------------------------------
__device__ __forceinline__ uint32_t smem_u32(const void* p) {
    uint32_t a;
    asm("{ .reg .u64 t; cvta.to.shared.u64 t, %1; cvt.u32.u64 %0, t; }"
        : "=r"(a) : "l"(p));
    return a;
}
__device__ __forceinline__ void cp16(uint32_t dst, const void* src) {
    asm volatile("cp.async.cg.shared.global [%0], [%1], 16;"
                 :: "r"(dst), "l"(src));
}
__device__ __forceinline__ void cp_commit() {
    asm volatile("cp.async.commit_group;" ::: "memory");
}
template<int N> __device__ __forceinline__ void cp_wait() {
    asm volatile("cp.async.wait_group %0;" :: "n"(N) : "memory");
}
__device__ __forceinline__ void ldsm4(uint32_t* r, uint32_t a) {
    asm volatile("ldmatrix.sync.aligned.m8n8.x4.shared.b16 {%0,%1,%2,%3}, [%4];"
        : "=r"(r[0]), "=r"(r[1]), "=r"(r[2]), "=r"(r[3]) : "r"(a));
}
__device__ __forceinline__ void ldsm4t(uint32_t* r, uint32_t a) {
    asm volatile("ldmatrix.sync.aligned.m8n8.x4.trans.shared.b16 {%0,%1,%2,%3}, [%4];"
        : "=r"(r[0]), "=r"(r[1]), "=r"(r[2]), "=r"(r[3]) : "r"(a));
}
__device__ __forceinline__ void mma16816(float* c, const uint32_t* a,
                                         uint32_t b0, uint32_t b1) {
    asm volatile(
        "mma.sync.aligned.m16n8k16.row.col.f32.bf16.bf16.f32 "
        "{%0,%1,%2,%3}, {%4,%5,%6,%7}, {%8,%9}, {%0,%1,%2,%3};"
        : "+f"(c[0]), "+f"(c[1]), "+f"(c[2]), "+f"(c[3])
        : "r"(a[0]), "r"(a[1]), "r"(a[2]), "r"(a[3]), "r"(b0), "r"(b1));
}

// ---------------------------------------------------------------------------
// Ragged max-pool -> bf16 hi/lo activations  act[batch][feat]
// ---------------------------------------------------------------------------
__global__ void pool_kernel(const float* __restrict__ x,
                            const float* __restrict__ xa,
                            const int*   __restrict__ lens,
                            __nv_bfloat16* __restrict__ actH,
                            __nv_bfloat16* __restrict__ actL)
{
    int warp = (blockIdx.x * blockDim.x + threadIdx.x) >> 5;
    int lane = threadIdx.x & 31;
    if (warp >= BATCH * DIM) return;
    int b = warp >> 12;
    int d = warp & 4095;

    const float* src = (d < 2048)
        ? (x  + ((size_t)(b * 2048 + d)        ) * VIEWS)
        : (xa + ((size_t)(b * 2048 + (d - 2048))) * VIEWS);

    int len = lens[b];
    len = max(1, min(len, VIEWS));

    float m = -FLT_MAX;
    for (int v0 = lane * 4; v0 < len; v0 += 128) {
        float4 v = *reinterpret_cast<const float4*>(src + v0);
        m = fmaxf(m, v.x);
        if (v0 + 1 < len) m = fmaxf(m, v.y);
        if (v0 + 2 < len) m = fmaxf(m, v.z);
        if (v0 + 3 < len) m = fmaxf(m, v.w);
    }
    #pragma unroll
    for (int o = 16; o; o >>= 1)
        m = fmaxf(m, __shfl_xor_sync(0xffffffffu, m, o));

    if (lane == 0) {
        __nv_bfloat16 h = __float2bfloat16(m);
        actH[warp] = h;
        actL[warp] = __float2bfloat16(m - __bfloat162float(h));
    }
}

// ---------------------------------------------------------------------------
// GEMM template: part[ks][feat][batch] = act[64,kchunk] @ W[kchunk, NT-tile]
//   grid (ceil(N/NT), KSPLIT), 256 threads = 8 warps (2m x 4n)
//   NT=128: warp m32 x n32 ; NT=64: warp m32 x n16
//   smem: 2 stages x { WH | WL | AH 8K | AL 8K }
// ---------------------------------------------------------------------------
template<int NT>
__global__ void __launch_bounds__(256) gemm_mma(
    const float* __restrict__ W, int N,
    const __nv_bfloat16* __restrict__ actH,
    const __nv_bfloat16* __restrict__ actL,
    float* __restrict__ partBase, int kchunk)
{
    constexpr int RB     = NT * 2;          // W smem row bytes
    constexpr int WBYTES = 64 * RB;         // one polarity W tile
    constexpr int OFF_WL = WBYTES;
    constexpr int OFF_AH = 2 * WBYTES;
    constexpr int OFF_AL = 2 * WBYTES + 8192;
    constexpr int STG    = 2 * WBYTES + 16384;
    constexpr int NJ     = NT / 16;         // float4/thread for W tile
    constexpr int WNW    = NT / 4;          // warp n width
    constexpr int NTT    = NT / 64;         // n16 ldsm tiles per warp

    extern __shared__ char smraw[];
    const uint32_t s0 = (smem_u32(smraw) + 1023) & ~1023u;
    const int tid = threadIdx.x;
    const int warp = tid >> 5, lane = tid & 31;
    const int warpM = warp & 1;
    const int warpN = warp >> 1;
    const int n0 = blockIdx.x * NT;
    const int kb = blockIdx.y * kchunk;
    float* part = partBase + (size_t)blockIdx.y * (DIM * BATCH);
    const int nst = kchunk >> 6;

    // W fp32 load: 4 threads per k-row
    const int wk = tid >> 2;
    const int wn = (tid & 3) * WNW;
    const float* wgp = W + (size_t)(kb + wk) * N + n0 + wn;
    const uint32_t wswz = (uint32_t)(wk & 7) << 4;
    const uint32_t wsrow = (uint32_t)wk * RB;

    // A cp.async: 4 threads per m-row, 2 x 16B each
    const int am = tid >> 2;
    const int akb = (tid & 3) * 16;
    const __nv_bfloat16* agpH = actH + (size_t)am * DIM + kb + akb;
    const __nv_bfloat16* agpL = actL + (size_t)am * DIM + kb + akb;
    uint32_t aoffc[2];
    #pragma unroll
    for (int c = 0; c < 2; ++c)
        aoffc[c] = (uint32_t)am * 128
                 + (((uint32_t)(akb * 2 + c * 16)) ^ ((uint32_t)(am & 7) << 4));

    const uint32_t arow = (lane & 7) + ((lane >> 3) & 1) * 8;
    const uint32_t ak2  = ((lane >> 4) & 1) * 16;
    const uint32_t aswz = (uint32_t)(lane & 7) << 4;

    const uint32_t brow  = (lane & 7) + ((lane >> 3) & 1) * 8;
    const uint32_t bhalf = ((lane >> 4) & 1) * 8;

    float acc[2][2 * NTT][4];
    #pragma unroll
    for (int i = 0; i < 2; ++i)
        #pragma unroll
        for (int j = 0; j < 2 * NTT; ++j)
            #pragma unroll
            for (int q = 0; q < 4; ++q) acc[i][j][q] = 0.f;

    float4 wreg[NJ];

    auto loadW = [&](int s) {
        const float* p = wgp + (size_t)s * 64 * N;
        #pragma unroll
        for (int j = 0; j < NJ; ++j) {
            int col = n0 + wn + j * 4;
            if (col + 3 < N) {
                wreg[j] = *reinterpret_cast<const float4*>(p + j * 4);
            } else {
                float4 v;
                v.x = (col + 0 < N) ? p[j * 4 + 0] : 0.f;
                v.y = (col + 1 < N) ? p[j * 4 + 1] : 0.f;
                v.z = (col + 2 < N) ? p[j * 4 + 2] : 0.f;
                v.w = (col + 3 < N) ? p[j * 4 + 3] : 0.f;
                wreg[j] = v;
            }
        }
    };
    auto storeW = [&](int buf) {
        const uint32_t base = s0 + buf * STG + wsrow;
        #pragma unroll
        for (int j = 0; j < NJ; ++j) {
            uint32_t off = ((uint32_t)((wn + j * 4) * 2)) ^ wswz;
            float4 f = wreg[j];
            uint32_t h01, h23, l01, l23;
            asm("cvt.rn.satfinite.bf16x2.f32 %0, %1, %2;" : "=r"(h01) : "f"(f.y), "f"(f.x));
            asm("cvt.rn.satfinite.bf16x2.f32 %0, %1, %2;" : "=r"(h23) : "f"(f.w), "f"(f.z));
            float l0 = f.x - __uint_as_float(h01 << 16);
            float l1 = f.y - __uint_as_float(h01 & 0xffff0000u);
            float l2 = f.z - __uint_as_float(h23 << 16);
            float l3 = f.w - __uint_as_float(h23 & 0xffff0000u);
            asm("cvt.rn.satfinite.bf16x2.f32 %0, %1, %2;" : "=r"(l01) : "f"(l1), "f"(l0));
            asm("cvt.rn.satfinite.bf16x2.f32 %0, %1, %2;" : "=r"(l23) : "f"(l3), "f"(l2));
            asm volatile("st.shared.v2.b32 [%0], {%1,%2};"
                         :: "r"(base + off), "r"(h01), "r"(h23));
            asm volatile("st.shared.v2.b32 [%0], {%1,%2};"
                         :: "r"(base + OFF_WL + off), "r"(l01), "r"(l23));
        }
    };
    auto issueA = [&](int s, int buf) {
        const uint32_t base = s0 + buf * STG;
        #pragma unroll
        for (int c = 0; c < 2; ++c) {
            cp16(base + OFF_AH + aoffc[c], agpH + s * 64 + c * 8);
            cp16(base + OFF_AL + aoffc[c], agpL + s * 64 + c * 8);
        }
        cp_commit();
    };
    auto compute = [&](int buf) {
        const uint32_t base = s0 + buf * STG;
        #pragma unroll
        for (int ks = 0; ks < 4; ++ks) {
            uint32_t bh[NTT][4], bl[NTT][4];
            #pragma unroll
            for (int nt = 0; nt < NTT; ++nt) {
                uint32_t bcol = ((uint32_t)((warpN * WNW + nt * 16 + bhalf) * 2))
                              ^ ((uint32_t)(lane & 7) << 4);
                uint32_t boff = (uint32_t)(ks * 16 + brow) * RB + bcol;
                ldsm4t(bh[nt], base + boff);
                ldsm4t(bl[nt], base + OFF_WL + boff);
            }
            const uint32_t kx = (uint32_t)(ks * 32 + ak2) ^ aswz;
            #pragma unroll
            for (int mt = 0; mt < 2; ++mt) {
                const uint32_t arow0 = (uint32_t)(warpM * 32 + mt * 16) * 128
                                     + arow * 128 + kx;
                uint32_t ah[4], al[4];
                ldsm4(ah, base + OFF_AH + arow0);
                ldsm4(al, base + OFF_AL + arow0);
                #pragma unroll
                for (int nt = 0; nt < NTT; ++nt) {
                    mma16816(acc[mt][nt * 2 + 0], ah, bh[nt][0], bh[nt][1]);
                    mma16816(acc[mt][nt * 2 + 1], ah, bh[nt][2], bh[nt][3]);
                    mma16816(acc[mt][nt * 2 + 0], al, bh[nt][0], bh[nt][1]);
                    mma16816(acc[mt][nt * 2 + 1], al, bh[nt][2], bh[nt][3]);
                    mma16816(acc[mt][nt * 2 + 0], ah, bl[nt][0], bl[nt][1]);
                    mma16816(acc[mt][nt * 2 + 1], ah, bl[nt][2], bl[nt][3]);
                }
            }
        }
    };

    // ---- single-barrier pipeline ----
    // iter s: storeW(s)->buf ; loadW(s+1) ; wait A(s) ; SYNC ;
    //         issueA(s+1)->buf^1 (safe: all warps past compute(buf^1)) ;
    //         compute(buf)
    issueA(0, 0);
    loadW(0);
    for (int s = 0; s < nst; ++s) {
        const int buf = s & 1;
        storeW(buf);
        if (s + 1 < nst) loadW(s + 1);
        cp_wait<0>();
        __syncthreads();
        if (s + 1 < nst) issueA(s + 1, buf ^ 1);
        compute(buf);
    }

    // epilogue: scatter f32 partials  part[feat*64 + batch]
    const int g = lane >> 2, tg = lane & 3;
    #pragma unroll
    for (int mt = 0; mt < 2; ++mt)
        #pragma unroll
        for (int nt = 0; nt < 2 * NTT; ++nt) {
            int feat = n0 + warpN * WNW + nt * 8 + tg * 2;
            int bat  = warpM * 32 + mt * 16 + g;
            float* p = part + (size_t)feat * 64 + bat;
            p[0]      = acc[mt][nt][0];
            p[64]     = acc[mt][nt][1];
            p[8]      = acc[mt][nt][2];
            p[64 + 8] = acc[mt][nt][3];
        }
}

// ---------------------------------------------------------------------------
// Reduce K-splits + bias + relu -> next-layer bf16 hi/lo activations
// ---------------------------------------------------------------------------
__global__ void reduce_bias_relu(const float* __restrict__ bias,
                                 __nv_bfloat16* __restrict__ actH,
                                 __nv_bfloat16* __restrict__ actL)
{
    int idx = blockIdx.x * 256 + threadIdx.x;   // 64*4096
    int n = idx >> 12;       // batch
    int m = idx & 4095;      // feat
    float s = bias[m];
    #pragma unroll
    for (int z = 0; z < 8; ++z) s += g_part[z][m * 64 + n];
    s = fmaxf(s, 0.f);
    __nv_bfloat16 h = __float2bfloat16(s);
    actH[idx] = h;
    actL[idx] = __float2bfloat16(s - __bfloat162float(h));
}

__global__ void reduce_out(const float* __restrict__ b3,
                           float* __restrict__ out)
{
    int idx = blockIdx.x * 256 + threadIdx.x;
    if (idx >= BATCH * OUTN) return;
    int n = idx / OUTN;      // batch
    int m = idx - n * OUTN;  // feat
    float s = b3[m];
    #pragma unroll
    for (int z = 0; z < 16; ++z) s += g_part[z][m * 64 + n];
    out[idx] = s;
}

// ---------------------------------------------------------------------------
// launch
// ---------------------------------------------------------------------------
extern "C" void kernel_launch(void* const* d_in, const int* in_sizes, int n_in,
                              void* d_out, int out_size)
{
    const float* x    = (const float*)d_in[0];
    const float* xa   = (const float*)d_in[1];
    const int*   lens = (const int*)  d_in[2];
    const float* w1   = (const float*)d_in[3];
    const float* b1   = (const float*)d_in[4];
    const float* w2   = (const float*)d_in[5];
    const float* b2   = (const float*)d_in[6];
    const float* w3   = (const float*)d_in[7];
    const float* b3   = (const float*)d_in[8];
    float* out = (float*)d_out;

    __nv_bfloat16 *actH, *actL;
    float* part;
    cudaGetSymbolAddress((void**)&actH, g_actH);
    cudaGetSymbolAddress((void**)&actL, g_actL);
    cudaGetSymbolAddress((void**)&part, g_part);

    const int SMEM128 = 2 * (2 * 64 * 256 + 16384) + 1024;   // 99328
    const int SMEM64  = 2 * (2 * 64 * 128 + 16384) + 1024;   // 66560
    cudaFuncSetAttribute(gemm_mma<128>,
                         cudaFuncAttributeMaxDynamicSharedMemorySize, SMEM128);
    cudaFuncSetAttribute(gemm_mma<64>,
                         cudaFuncAttributeMaxDynamicSharedMemorySize, SMEM64);

    // 1) pool -> act hi/lo
    {
        int warps = BATCH * DIM;
        int blocks = (warps * 32 + 255) / 256;
        pool_kernel<<<blocks, 256>>>(x, xa, lens, actH, actL);
    }
    // 2) layer 1: 32 n-tiles x ksplit 8 (kchunk 512, 8 stages)
    gemm_mma<128><<<dim3(32, 8), 256, SMEM128>>>(w1, DIM, actH, actL, part, 512);
    reduce_bias_relu<<<1024, 256>>>(b1, actH, actL);
    // 3) layer 2
    gemm_mma<128><<<dim3(32, 8), 256, SMEM128>>>(w2, DIM, actH, actL, part, 512);
    reduce_bias_relu<<<1024, 256>>>(b2, actH, actL);
    // 4) layer 3: N=1000 -> 16 n64-tiles x ksplit 16 (kchunk 256, 4 stages)
    gemm_mma<64><<<dim3(16, 16), 256, SMEM64>>>(w3, OUTN, actH, actL, part, 256);
    reduce_out<<<(BATCH * OUTN + 255) / 256, 256>>>(b3, out);
}